// round 1
// baseline (speedup 1.0000x reference)
#include <cuda_runtime.h>
#include <math.h>

#define NUM_ITEMS  10000
#define NUM_USERS  10000
#define NUM_GROUPS 5000
#define EMB_DIM    64
#define BATCH      16384

// Scratch (allocation-free rule: __device__ globals)
__device__ float g_user_embeds[NUM_USERS * EMB_DIM];   // 2.56 MB
__device__ float g_group_embeds[NUM_GROUPS * EMB_DIM]; // 1.28 MB

// ---------------------------------------------------------------------------
// Sparse-aware row aggregation: one warp per output row.
//   out[row] = (sum_{j : mat[row][j] > 0} emb[j]) / divisor
// divisor = max(count,1) if CLAMP else count (raw sum of binary row).
// Row scan is a coalesced float4 stream (512 B per warp-iteration);
// nonzero hits gather a 256 B embedding row cooperatively (float2 per lane).
// ---------------------------------------------------------------------------
template <int NCOLS, bool CLAMP>
__global__ void row_aggregate_kernel(const float* __restrict__ mat,
                                     const float* __restrict__ emb,
                                     float* __restrict__ out,
                                     int nrows)
{
    const int warps_per_block = blockDim.x >> 5;
    const int warp_id  = threadIdx.x >> 5;
    const int lane     = threadIdx.x & 31;
    const int row      = blockIdx.x * warps_per_block + warp_id;
    if (row >= nrows) return;

    const int ncols4 = NCOLS / 4;  // NCOLS divisible by 4 (10000)
    const float4* __restrict__ row4 =
        (const float4*)(mat + (size_t)row * NCOLS);
    const float2* __restrict__ emb2 = (const float2*)emb;  // [item][32] float2

    float2 acc = make_float2(0.f, 0.f);
    int cnt = 0;

    for (int base = 0; base < ncols4; base += 32) {
        const int j4 = base + lane;
        float4 v;
        if (j4 < ncols4) v = row4[j4];
        else             v = make_float4(0.f, 0.f, 0.f, 0.f);

        #pragma unroll
        for (int c = 0; c < 4; ++c) {
            const float vc = (&v.x)[c];
            unsigned m = __ballot_sync(0xffffffffu, vc > 0.f);
            cnt += __popc(m);
            while (m) {
                const int l = __ffs(m) - 1;
                m &= m - 1;
                const int item = (base + l) * 4 + c;
                const float2 e = emb2[item * 32 + lane];
                acc.x += e.x;
                acc.y += e.y;
            }
        }
    }

    float div = (float)cnt;
    if (CLAMP) div = fmaxf(div, 1.0f);
    const float inv = 1.0f / div;

    float2* __restrict__ out2 = (float2*)(out + (size_t)row * EMB_DIM);
    out2[lane] = make_float2(acc.x * inv, acc.y * inv);
}

// ---------------------------------------------------------------------------
// MLP: y = sigmoid(relu([ge[g], ie[it]] @ W1 + b1) @ W2 + b2)
// One thread per batch element; weights staged in shared.
// ---------------------------------------------------------------------------
__global__ void mlp_kernel(const float* __restrict__ group_embeds,
                           const float* __restrict__ item_emb,
                           const float* __restrict__ W1,  // [128, 8]
                           const float* __restrict__ b1,  // [8]
                           const float* __restrict__ W2,  // [8, 1]
                           const float* __restrict__ b2,  // [1]
                           const int*   __restrict__ gidx,
                           const int*   __restrict__ iidx,
                           float* __restrict__ out,
                           int batch)
{
    __shared__ float sW1[2 * EMB_DIM * 8];
    __shared__ float sb1[8];
    __shared__ float sW2[8];
    __shared__ float sb2;

    for (int i = threadIdx.x; i < 2 * EMB_DIM * 8; i += blockDim.x)
        sW1[i] = W1[i];
    if (threadIdx.x < 8) {
        sb1[threadIdx.x] = b1[threadIdx.x];
        sW2[threadIdx.x] = W2[threadIdx.x];
    }
    if (threadIdx.x == 0) sb2 = b2[0];
    __syncthreads();

    const int i = blockIdx.x * blockDim.x + threadIdx.x;
    if (i >= batch) return;

    const int g  = gidx[i];
    const int it = iidx[i];
    const float2* __restrict__ ge2 =
        (const float2*)(group_embeds + (size_t)g * EMB_DIM);
    const float2* __restrict__ ie2 =
        (const float2*)(item_emb + (size_t)it * EMB_DIM);

    float h[8];
    #pragma unroll
    for (int k = 0; k < 8; ++k) h[k] = sb1[k];

    // first half: group embedding (dims 0..63 of the concat)
    #pragma unroll 4
    for (int d2 = 0; d2 < 32; ++d2) {
        const float2 e = ge2[d2];
        const int d0 = 2 * d2;
        #pragma unroll
        for (int k = 0; k < 8; ++k) {
            h[k] += e.x * sW1[(d0    ) * 8 + k];
            h[k] += e.y * sW1[(d0 + 1) * 8 + k];
        }
    }
    // second half: item embedding (dims 64..127 of the concat)
    #pragma unroll 4
    for (int d2 = 0; d2 < 32; ++d2) {
        const float2 e = ie2[d2];
        const int d0 = 2 * d2 + EMB_DIM;
        #pragma unroll
        for (int k = 0; k < 8; ++k) {
            h[k] += e.x * sW1[(d0    ) * 8 + k];
            h[k] += e.y * sW1[(d0 + 1) * 8 + k];
        }
    }

    float y = sb2;
    #pragma unroll
    for (int k = 0; k < 8; ++k)
        y += fmaxf(h[k], 0.0f) * sW2[k];

    out[i] = 1.0f / (1.0f + expf(-y));
}

// ---------------------------------------------------------------------------
// Launch: inputs in metadata order:
//   0 item_emb [10000,64] f32   1 ui [10000,10000] f32   2 gu [5000,10000] f32
//   3 W1 [128,8]   4 b1 [8]   5 W2 [8,1]   6 b2 [1]
//   7 group_inputs [16384] i32   8 item_inputs [16384] i32
// Output: [16384,1] f32
// ---------------------------------------------------------------------------
extern "C" void kernel_launch(void* const* d_in, const int* in_sizes, int n_in,
                              void* d_out, int out_size)
{
    const float* item_emb = (const float*)d_in[0];
    const float* ui       = (const float*)d_in[1];
    const float* gu       = (const float*)d_in[2];
    const float* W1       = (const float*)d_in[3];
    const float* b1       = (const float*)d_in[4];
    const float* W2       = (const float*)d_in[5];
    const float* b2       = (const float*)d_in[6];
    const int*   gidx     = (const int*)d_in[7];
    const int*   iidx     = (const int*)d_in[8];
    float* out            = (float*)d_out;

    float* user_embeds;
    float* group_embeds;
    cudaGetSymbolAddress((void**)&user_embeds,  g_user_embeds);
    cudaGetSymbolAddress((void**)&group_embeds, g_group_embeds);

    // Kernel 1: user_embeds = (ui @ item_emb) / clamp(count, 1)
    {
        const int threads = 256;                  // 8 warps -> 8 rows/block
        const int rows_per_block = threads / 32;
        const int grid = (NUM_USERS + rows_per_block - 1) / rows_per_block;
        row_aggregate_kernel<NUM_ITEMS, true>
            <<<grid, threads>>>(ui, item_emb, user_embeds, NUM_USERS);
    }

    // Kernel 2: group_embeds = (gu @ user_embeds) / count   (raw, no clamp)
    {
        const int threads = 256;
        const int rows_per_block = threads / 32;
        const int grid = (NUM_GROUPS + rows_per_block - 1) / rows_per_block;
        row_aggregate_kernel<NUM_USERS, false>
            <<<grid, threads>>>(gu, user_embeds, group_embeds, NUM_GROUPS);
    }

    // Kernel 3: MLP head
    {
        const int threads = 128;
        const int grid = (BATCH + threads - 1) / threads;
        mlp_kernel<<<grid, threads>>>(group_embeds, item_emb,
                                      W1, b1, W2, b2, gidx, iidx,
                                      out, BATCH);
    }
}

// round 2
// speedup vs baseline: 1.3748x; 1.3748x over previous
#include <cuda_runtime.h>
#include <math.h>

#define NUM_ITEMS  10000
#define NUM_USERS  10000
#define NUM_GROUPS 5000
#define EMB_DIM    64
#define BATCH      16384

// Scratch (allocation-free rule: __device__ globals)
__device__ float g_user_embeds[NUM_USERS * EMB_DIM];   // 2.56 MB
__device__ float g_group_embeds[NUM_GROUPS * EMB_DIM]; // 1.28 MB

// ---------------------------------------------------------------------------
// Sparse-aware row aggregation, one warp per output row, deep prefetch.
//   out[row] = (sum_{j : mat[row][j] > 0} emb[j]) / divisor
// UNROLL independent float4 loads are issued before any consume -> MLP ~ 8.
// One ballot per float4 chunk group (4-bit lane masks + shfl).
// ---------------------------------------------------------------------------
template <int NCOLS, bool CLAMP>
__global__ void row_aggregate_kernel(const float* __restrict__ mat,
                                     const float* __restrict__ emb,
                                     float* __restrict__ out,
                                     int nrows)
{
    constexpr int UNROLL = 8;                  // prefetch depth (float4 per lane)
    const int warps_per_block = blockDim.x >> 5;
    const int warp_id  = threadIdx.x >> 5;
    const int lane     = threadIdx.x & 31;
    const int row      = blockIdx.x * warps_per_block + warp_id;
    if (row >= nrows) return;

    const int ncols4 = NCOLS / 4;              // 2500 for NCOLS=10000
    const float4* __restrict__ row4 =
        (const float4*)(mat + (size_t)row * NCOLS);
    const float2* __restrict__ emb2 = (const float2*)emb;

    float2 acc = make_float2(0.f, 0.f);
    int mycnt = 0;                             // per-lane count, reduced at end

    for (int base = 0; base < ncols4; base += 32 * UNROLL) {
        // ---- issue all UNROLL loads up front (independent -> MLP=UNROLL) ----
        float4 v[UNROLL];
        #pragma unroll
        for (int u = 0; u < UNROLL; ++u) {
            const int j4 = base + u * 32 + lane;
            if (j4 < ncols4) v[u] = row4[j4];
            else             v[u] = make_float4(0.f, 0.f, 0.f, 0.f);
        }

        // ---- consume ----
        #pragma unroll
        for (int u = 0; u < UNROLL; ++u) {
            const int chunk = base + u * 32;   // float4 index of lane 0
            unsigned lm = 0;
            lm |= (v[u].x > 0.f) ? 1u : 0u;
            lm |= (v[u].y > 0.f) ? 2u : 0u;
            lm |= (v[u].z > 0.f) ? 4u : 0u;
            lm |= (v[u].w > 0.f) ? 8u : 0u;
            mycnt += __popc(lm);

            unsigned hm = __ballot_sync(0xffffffffu, lm != 0u);
            while (hm) {                       // hm uniform across warp
                const int l = __ffs(hm) - 1;
                hm &= hm - 1;
                unsigned lmask = __shfl_sync(0xffffffffu, lm, l);
                const int itembase = (chunk + l) * 4;
                while (lmask) {
                    const int c = __ffs(lmask) - 1;
                    lmask &= lmask - 1;
                    const float2 e = emb2[(itembase + c) * 32 + lane];
                    acc.x += e.x;
                    acc.y += e.y;
                }
            }
        }
    }

    int cnt = __reduce_add_sync(0xffffffffu, mycnt);
    float div = (float)cnt;
    if (CLAMP) div = fmaxf(div, 1.0f);
    const float inv = 1.0f / div;

    float2* __restrict__ out2 = (float2*)(out + (size_t)row * EMB_DIM);
    out2[lane] = make_float2(acc.x * inv, acc.y * inv);
}

// ---------------------------------------------------------------------------
// MLP: y = sigmoid(relu([ge[g], ie[it]] @ W1 + b1) @ W2 + b2)
// ---------------------------------------------------------------------------
__global__ void mlp_kernel(const float* __restrict__ group_embeds,
                           const float* __restrict__ item_emb,
                           const float* __restrict__ W1,  // [128, 8]
                           const float* __restrict__ b1,  // [8]
                           const float* __restrict__ W2,  // [8, 1]
                           const float* __restrict__ b2,  // [1]
                           const int*   __restrict__ gidx,
                           const int*   __restrict__ iidx,
                           float* __restrict__ out,
                           int batch)
{
    __shared__ float sW1[2 * EMB_DIM * 8];
    __shared__ float sb1[8];
    __shared__ float sW2[8];
    __shared__ float sb2;

    for (int i = threadIdx.x; i < 2 * EMB_DIM * 8; i += blockDim.x)
        sW1[i] = W1[i];
    if (threadIdx.x < 8) {
        sb1[threadIdx.x] = b1[threadIdx.x];
        sW2[threadIdx.x] = W2[threadIdx.x];
    }
    if (threadIdx.x == 0) sb2 = b2[0];
    __syncthreads();

    const int i = blockIdx.x * blockDim.x + threadIdx.x;
    if (i >= batch) return;

    const int g  = gidx[i];
    const int it = iidx[i];
    const float2* __restrict__ ge2 =
        (const float2*)(group_embeds + (size_t)g * EMB_DIM);
    const float2* __restrict__ ie2 =
        (const float2*)(item_emb + (size_t)it * EMB_DIM);

    float h[8];
    #pragma unroll
    for (int k = 0; k < 8; ++k) h[k] = sb1[k];

    #pragma unroll 4
    for (int d2 = 0; d2 < 32; ++d2) {
        const float2 e = ge2[d2];
        const int d0 = 2 * d2;
        #pragma unroll
        for (int k = 0; k < 8; ++k) {
            h[k] += e.x * sW1[(d0    ) * 8 + k];
            h[k] += e.y * sW1[(d0 + 1) * 8 + k];
        }
    }
    #pragma unroll 4
    for (int d2 = 0; d2 < 32; ++d2) {
        const float2 e = ie2[d2];
        const int d0 = 2 * d2 + EMB_DIM;
        #pragma unroll
        for (int k = 0; k < 8; ++k) {
            h[k] += e.x * sW1[(d0    ) * 8 + k];
            h[k] += e.y * sW1[(d0 + 1) * 8 + k];
        }
    }

    float y = sb2;
    #pragma unroll
    for (int k = 0; k < 8; ++k)
        y += fmaxf(h[k], 0.0f) * sW2[k];

    out[i] = 1.0f / (1.0f + expf(-y));
}

// ---------------------------------------------------------------------------
extern "C" void kernel_launch(void* const* d_in, const int* in_sizes, int n_in,
                              void* d_out, int out_size)
{
    const float* item_emb = (const float*)d_in[0];
    const float* ui       = (const float*)d_in[1];
    const float* gu       = (const float*)d_in[2];
    const float* W1       = (const float*)d_in[3];
    const float* b1       = (const float*)d_in[4];
    const float* W2       = (const float*)d_in[5];
    const float* b2       = (const float*)d_in[6];
    const int*   gidx     = (const int*)d_in[7];
    const int*   iidx     = (const int*)d_in[8];
    float* out            = (float*)d_out;

    float* user_embeds;
    float* group_embeds;
    cudaGetSymbolAddress((void**)&user_embeds,  g_user_embeds);
    cudaGetSymbolAddress((void**)&group_embeds, g_group_embeds);

    // Kernel 1: user_embeds = (ui @ item_emb) / clamp(count, 1)
    {
        const int threads = 256;                  // 8 warps -> 8 rows/block
        const int rows_per_block = threads / 32;
        const int grid = (NUM_USERS + rows_per_block - 1) / rows_per_block;
        row_aggregate_kernel<NUM_ITEMS, true>
            <<<grid, threads>>>(ui, item_emb, user_embeds, NUM_USERS);
    }

    // Kernel 2: group_embeds = (gu @ user_embeds) / count   (raw, no clamp)
    {
        const int threads = 256;
        const int rows_per_block = threads / 32;
        const int grid = (NUM_GROUPS + rows_per_block - 1) / rows_per_block;
        row_aggregate_kernel<NUM_USERS, false>
            <<<grid, threads>>>(gu, user_embeds, group_embeds, NUM_GROUPS);
    }

    // Kernel 3: MLP head
    {
        const int threads = 128;
        const int grid = (BATCH + threads - 1) / threads;
        mlp_kernel<<<grid, threads>>>(group_embeds, item_emb,
                                      W1, b1, W2, b2, gidx, iidx,
                                      out, BATCH);
    }
}